// round 16
// baseline (speedup 1.0000x reference)
#include <cuda_runtime.h>
#include <cuda_bf16.h>
#include <math.h>
#include <stdint.h>

// Problem constants
#define D_DIM 1024
#define B_DIM 32
#define NBLK  128      // 4 groups x 32 blocks, 1 CTA/SM, all co-resident
#define NGROUP 4
#define GSZ    32      // blocks per group
#define BSUB   8       // batches per group

// -------------------- device scratch (no cudaMalloc allowed) --------------------
__device__ float g_scale;
__device__ float g_WxHi[D_DIM * D_DIM];            // W_x tf32 hi split
__device__ float g_WxLo[D_DIM * D_DIM];            // W_x tf32 lo split
// packed bf16 recurrent state, mma-B-fragment layout:
// [group][parity][sblk(64)][tig(4)][gid(8)] -> uint4 (bhi0,bhi1,blo0,blo1)
__device__ uint32_t g_spack[NGROUP][2][64 * 4 * 8 * 4];
__device__ __align__(16) unsigned g_flag[NGROUP][GSZ];   // producer publish counters

// -------------------- block-wide sum over 1024 threads --------------------
__device__ __forceinline__ float block_sum1024(float v) {
    __shared__ float sr[32];
    __shared__ float res;
    #pragma unroll
    for (int o = 16; o; o >>= 1) v += __shfl_xor_sync(0xffffffffu, v, o);
    if ((threadIdx.x & 31) == 0) sr[threadIdx.x >> 5] = v;
    __syncthreads();
    if (threadIdx.x < 32) {
        float t = sr[threadIdx.x];
        #pragma unroll
        for (int o = 16; o; o >>= 1) t += __shfl_xor_sync(0xffffffffu, t, o);
        if (threadIdx.x == 0) res = t;
    }
    __syncthreads();
    float out = res;
    __syncthreads();
    return out;
}

// -------------------- 1) spectral norm power iteration --------------------
__global__ void spectral_kernel(const float* __restrict__ Wh,
                                const float* __restrict__ u0) {
    __shared__ float su[D_DIM];
    __shared__ float sv[D_DIM];
    __shared__ float sraw[D_DIM];
    const int tid  = threadIdx.x;
    const int w    = tid >> 5;
    const int lane = tid & 31;

    float x0 = u0[tid];
    float n0 = sqrtf(block_sum1024(x0 * x0));
    su[tid] = x0 / n0;
    __syncthreads();

    for (int it = 0; it < 3; it++) {
        {   // v = W^T u
            float a = 0.f;
            const float* col = Wh + tid;
            #pragma unroll 4
            for (int i = 0; i < D_DIM; i++)
                a = fmaf(col[(size_t)i * D_DIM], su[i], a);
            float nrm = sqrtf(block_sum1024(a * a));
            sv[tid] = a / (nrm + 1e-8f);
            __syncthreads();
        }
        {   // u_raw = W v
            for (int s = 0; s < 32; s++) {
                int r = w * 32 + s;
                const float* row = Wh + (size_t)r * D_DIM;
                float a = 0.f;
                #pragma unroll 4
                for (int k = lane; k < D_DIM; k += 32)
                    a = fmaf(row[k], sv[k], a);
                #pragma unroll
                for (int o = 16; o; o >>= 1) a += __shfl_xor_sync(0xffffffffu, a, o);
                if (lane == 0) sraw[r] = a;
            }
            __syncthreads();
            float rv  = sraw[tid];
            float nrm = sqrtf(block_sum1024(rv * rv));
            su[tid] = rv / (nrm + 1e-8f);
            __syncthreads();
        }
    }
    float sg = block_sum1024(su[tid] * sraw[tid]);
    if (tid == 0) g_scale = 0.99f / (fabsf(sg) + 1e-8f);
}

// -------------------- helpers --------------------
__device__ __forceinline__ void tf32_split(float v, float& h, float& l) {
    uint32_t hb; asm("cvt.rna.tf32.f32 %0, %1;" : "=r"(hb) : "f"(v));
    float hf = __uint_as_float(hb);
    float lv = v - hf;
    uint32_t lb; asm("cvt.rna.tf32.f32 %0, %1;" : "=r"(lb) : "f"(lv));
    h = hf; l = __uint_as_float(lb);
}

__device__ __forceinline__ void bf16_split(float v, __nv_bfloat16& h, __nv_bfloat16& l) {
    h = __float2bfloat16_rn(v);
    l = __float2bfloat16_rn(v - __bfloat162float(h));
}

// bf16-unit index into g_spack for state element (d, n): hi at uoff p>>2, lo at 2+(p>>2)
__device__ __forceinline__ int spack_idx(int d, int n, int is_lo) {
    int sblk = d >> 4;
    int kk   = d & 15;
    int p    = kk >> 1;
    int j    = kk & 1;
    int tigp = p & 3;
    int uoff = (is_lo ? 2 : 0) + (p >> 2);
    return (sblk * 128 + tigp * 32 + n * 4 + uoff) * 2 + j;
}

// -------------------- 2a) split W_x once (reused by all 512 m-tiles) --------------------
__global__ void wsplit_kernel(const float* __restrict__ Wx) {
    int i = blockIdx.x * blockDim.x + threadIdx.x;
    if (i < D_DIM * D_DIM) {
        float h, l;
        tf32_split(Wx[i], h, l);
        g_WxHi[i] = h;
        g_WxLo[i] = l;
    }
}

// -------------------- 2b) prep: pack h0 state, zero flags, copy h0 to output ----------
__global__ void prep_kernel(const float* __restrict__ h0,
                            float* __restrict__ hout0) {
    int i = blockIdx.x * blockDim.x + threadIdx.x;
    if (i < NGROUP * GSZ) g_flag[i >> 5][i & 31] = 0;   // replay-safe reset
    if (i < B_DIM * D_DIM) {
        int b = i >> 10;
        int d = i & (D_DIM - 1);
        int g = b >> 3;
        int n = b & 7;
        float v = h0[i];
        __nv_bfloat16 hi, lo;
        bf16_split(v, hi, lo);
        __nv_bfloat16* sp = (__nv_bfloat16*)g_spack[g][0];
        sp[spack_idx(d, n, 0)] = hi;
        sp[spack_idx(d, n, 1)] = lo;
        hout0[i] = v;
    }
}

// -------------------- 3) split-tf32 tensor-core GEMM (known-good 2.0ms) ----------
#define GS 36

__device__ __forceinline__ void mma_tf32(float* c, const uint32_t* a, const uint32_t* b) {
    asm volatile(
        "mma.sync.aligned.m16n8k8.row.col.f32.tf32.tf32.f32 "
        "{%0,%1,%2,%3}, {%4,%5,%6,%7}, {%8,%9}, {%0,%1,%2,%3};"
        : "+f"(c[0]), "+f"(c[1]), "+f"(c[2]), "+f"(c[3])
        : "r"(a[0]), "r"(a[1]), "r"(a[2]), "r"(a[3]), "r"(b[0]), "r"(b[1]));
}

__global__ __launch_bounds__(256, 2)
void gemm_tf32_kernel(const float* __restrict__ X,
                      float* __restrict__ C) {
    extern __shared__ float gsm[];
    float* Xh = gsm;
    float* Xl = Xh + 128 * GS;
    float* Wh = Xl + 128 * GS;
    float* Wl = Wh + 128 * GS;

    const float* __restrict__ WHi = g_WxHi;
    const float* __restrict__ WLo = g_WxLo;

    const int tid  = threadIdx.x;
    const int bn   = blockIdx.x * 128;
    const int bm   = blockIdx.y * 128;
    const int wid  = tid >> 5, lane = tid & 31;
    const int wm   = wid >> 2;
    const int wn   = wid & 3;
    const int gid  = lane >> 2, tig = lane & 3;

    float c[4][4][4];
    #pragma unroll
    for (int mt = 0; mt < 4; mt++)
        #pragma unroll
        for (int nt = 0; nt < 4; nt++)
            #pragma unroll
            for (int r = 0; r < 4; r++) c[mt][nt][r] = 0.f;

    const int sr = tid >> 3;
    const int sc = (tid & 7) * 4;

    for (int k0 = 0; k0 < D_DIM; k0 += 32) {
        __syncthreads();
        #pragma unroll
        for (int j = 0; j < 4; j++) {
            int row = sr + j * 32;
            float4 xv  = *(const float4*)&X[(size_t)(bm + row) * D_DIM + k0 + sc];
            float4 wvh = *(const float4*)&WHi[(size_t)(bn + row) * D_DIM + k0 + sc];
            float4 wvl = *(const float4*)&WLo[(size_t)(bn + row) * D_DIM + k0 + sc];
            float h, l;
            tf32_split(xv.x, h, l); Xh[row*GS+sc+0]=h; Xl[row*GS+sc+0]=l;
            tf32_split(xv.y, h, l); Xh[row*GS+sc+1]=h; Xl[row*GS+sc+1]=l;
            tf32_split(xv.z, h, l); Xh[row*GS+sc+2]=h; Xl[row*GS+sc+2]=l;
            tf32_split(xv.w, h, l); Xh[row*GS+sc+3]=h; Xl[row*GS+sc+3]=l;
            *(float4*)&Wh[row*GS+sc] = wvh;
            *(float4*)&Wl[row*GS+sc] = wvl;
        }
        __syncthreads();
        #pragma unroll
        for (int k8 = 0; k8 < 4; k8++) {
            const int kk = k8 * 8 + tig;
            uint32_t ah[4][4], al[4][4], bh[4][2], bl[4][2];
            #pragma unroll
            for (int mt = 0; mt < 4; mt++) {
                int r0 = wm * 64 + mt * 16 + gid;
                const float* p0 = &Xh[r0 * GS + kk];
                ah[mt][0] = __float_as_uint(p0[0]);
                ah[mt][1] = __float_as_uint(p0[8 * GS]);
                ah[mt][2] = __float_as_uint(p0[4]);
                ah[mt][3] = __float_as_uint(p0[8 * GS + 4]);
                const float* p1 = &Xl[r0 * GS + kk];
                al[mt][0] = __float_as_uint(p1[0]);
                al[mt][1] = __float_as_uint(p1[8 * GS]);
                al[mt][2] = __float_as_uint(p1[4]);
                al[mt][3] = __float_as_uint(p1[8 * GS + 4]);
            }
            #pragma unroll
            for (int nt = 0; nt < 4; nt++) {
                int c0n = wn * 32 + nt * 8 + gid;
                const float* p0 = &Wh[c0n * GS + kk];
                bh[nt][0] = __float_as_uint(p0[0]);
                bh[nt][1] = __float_as_uint(p0[4]);
                const float* p1 = &Wl[c0n * GS + kk];
                bl[nt][0] = __float_as_uint(p1[0]);
                bl[nt][1] = __float_as_uint(p1[4]);
            }
            #pragma unroll
            for (int mt = 0; mt < 4; mt++)
                #pragma unroll
                for (int nt = 0; nt < 4; nt++) {
                    mma_tf32(c[mt][nt], ah[mt], bh[nt]);
                    mma_tf32(c[mt][nt], ah[mt], bl[nt]);
                    mma_tf32(c[mt][nt], al[mt], bh[nt]);
                }
        }
    }
    #pragma unroll
    for (int mt = 0; mt < 4; mt++) {
        int row = bm + wm * 64 + mt * 16 + gid;
        #pragma unroll
        for (int nt = 0; nt < 4; nt++) {
            int col = bn + wn * 32 + nt * 8 + 2 * tig;
            *(float2*)&C[(size_t)row * D_DIM + col]       = make_float2(c[mt][nt][0], c[mt][nt][1]);
            *(float2*)&C[(size_t)(row + 8) * D_DIM + col] = make_float2(c[mt][nt][2], c[mt][nt][3]);
        }
    }
}

// -------------------- 4) persistent scan kernel (v8: flag sync, CORRECT fences) ------
// R10 mma recurrence + flag-based sync with proper memory ordering:
//   release: spack stores -> __threadfence() by ALL threads (drains only the 2
//            small L2-resident bf16 stores; heavy wx/hout stores issue AFTER the
//            fence) -> __syncthreads -> tid0 st.global.release flag.
//   acquire: lane 0 polls its warp's 4 producer flags with ld.global.acquire.gpu
//            (orders subsequent state loads without draining own pending stores).
// Warp w consumes d-slice [128w,128w+128) produced by blocks 4w..4w+3 only.
// The partials __syncthreads (union of all warps' polls = all 32 flags) preserves
// the double-buffer WAR invariant (any block leads any other by <= 1 step).
__device__ __forceinline__ void mma_bf16(float* c, const uint32_t* a, uint32_t b0, uint32_t b1) {
    asm volatile(
        "mma.sync.aligned.m16n8k16.row.col.f32.bf16.bf16.f32 "
        "{%0,%1,%2,%3}, {%4,%5,%6,%7}, {%8,%9}, {%0,%1,%2,%3};"
        : "+f"(c[0]), "+f"(c[1]), "+f"(c[2]), "+f"(c[3])
        : "r"(a[0]), "r"(a[1]), "r"(a[2]), "r"(a[3]), "r"(b0), "r"(b1));
}

__global__ __launch_bounds__(256, 1)
void scan_kernel(const float* __restrict__ Whmat,
                 float* __restrict__ wx_out,        // [T][B][D]: in = Wx, overwritten with out
                 float* __restrict__ hout,          // [T+1][B][D]
                 const float* __restrict__ bvec,
                 const float* __restrict__ bgvec,
                 int T) {
    __shared__ __align__(16) float red[10240];

    const int tid  = threadIdx.x;
    const int g    = blockIdx.x >> 5;     // group 0..3
    const int r    = blockIdx.x & 31;     // rank in group
    const int e0   = r * 32;
    const int b0   = g * BSUB;

    const int w    = tid >> 5;            // warp 0..7, covers k in [w*128, w*128+128)
    const int lane = tid & 31;
    const int gid  = lane >> 2;           // 0..7
    const int tig  = lane & 3;            // 0..3

    // ---- preload W A-fragments into registers (hi/lo bf16 split, scaled) ----
    const float s = g_scale;
    uint32_t Ah[2][8][4], Al[2][8][4];
    #pragma unroll
    for (int mt = 0; mt < 2; mt++) {
        #pragma unroll
        for (int ks = 0; ks < 8; ks++) {
            const int k0 = w * 128 + ks * 16 + 2 * tig;
            const int r0 = e0 + mt * 16 + gid;
            #pragma unroll
            for (int i = 0; i < 4; i++) {
                const int rr = r0 + ((i & 1) ? 8 : 0);
                const int kk = k0 + ((i & 2) ? 8 : 0);
                float f0 = Whmat[(size_t)rr * D_DIM + kk]     * s;
                float f1 = Whmat[(size_t)rr * D_DIM + kk + 1] * s;
                __nv_bfloat16 h0b, l0b, h1b, l1b;
                bf16_split(f0, h0b, l0b);
                bf16_split(f1, h1b, l1b);
                __nv_bfloat162 th; th.x = h0b; th.y = h1b;
                __nv_bfloat162 tl; tl.x = l0b; tl.y = l1b;
                Ah[mt][ks][i] = *(uint32_t*)&th;
                Al[mt][ks][i] = *(uint32_t*)&tl;
            }
        }
    }

    // epilogue mapping: thread -> (e = tid&31, b = tid>>5)
    const int eL = tid & 31;
    const int bO = tid >> 5;
    const float bb  = bvec[e0 + eL];
    const float bgg = bgvec[e0 + eL];
    const int oaddr = (eL * 8 + bO) * 40 + (eL & 3) * 8;   // reduce base (slots 0..7)
    const int pub_hi = spack_idx(e0 + eL, bO, 0);
    const int pub_lo = spack_idx(e0 + eL, bO, 1);

    const unsigned* quad_flags = &g_flag[g][4 * w];  // this warp's 4 producers
    unsigned* pubflag = &g_flag[g][r];

    __syncthreads();

    int par = 0;

    for (int t = 0; t < T; t++) {
        // prefetch Wx element (DRAM latency overlaps flag poll + mma loop)
        const size_t gidx = ((size_t)t * B_DIM + (b0 + bO)) * D_DIM + (e0 + eL);
        const float wxv = __ldcg(&wx_out[gidx]);

        // ---- wait for this warp's 4 producer blocks (lane 0, acquire loads) ----
        if (lane == 0) {
            const unsigned tgt = (unsigned)t;
            unsigned f0, f1, f2, f3;
            do {
                asm volatile("ld.global.acquire.gpu.u32 %0, [%4];\n\t"
                             "ld.global.acquire.gpu.u32 %1, [%4+4];\n\t"
                             "ld.global.acquire.gpu.u32 %2, [%4+8];\n\t"
                             "ld.global.acquire.gpu.u32 %3, [%4+12];"
                             : "=r"(f0), "=r"(f1), "=r"(f2), "=r"(f3)
                             : "l"(quad_flags) : "memory");
            } while (f0 < tgt || f1 < tgt || f2 < tgt || f3 < tgt);
        }
        __syncwarp();

        float c0[4] = {0.f, 0.f, 0.f, 0.f};
        float c1[4] = {0.f, 0.f, 0.f, 0.f};

        const uint4* bp = (const uint4*)g_spack[g][par];
        #pragma unroll
        for (int ks = 0; ks < 8; ks++) {
            uint4 v = __ldcg(&bp[(w * 8 + ks) * 32 + tig * 8 + gid]);
            // v = (bhi0, bhi1, blo0, blo1)
            mma_bf16(c0, Ah[0][ks], v.x, v.y);
            mma_bf16(c0, Ah[0][ks], v.z, v.w);
            mma_bf16(c0, Al[0][ks], v.x, v.y);
            mma_bf16(c1, Ah[1][ks], v.x, v.y);
            mma_bf16(c1, Ah[1][ks], v.z, v.w);
            mma_bf16(c1, Al[1][ks], v.x, v.y);
        }

        // ---- partials -> smem: value (e_loc, col) at (e_loc*8+col)*40 + (e_loc&3)*8 + w
        {
            const int rot = (gid & 3) * 8;
            int a0 = (gid * 8 + 2 * tig) * 40 + rot + w;
            red[a0]      = c0[0];
            red[a0 + 40] = c0[1];
            int a2 = ((gid + 8) * 8 + 2 * tig) * 40 + rot + w;
            red[a2]      = c0[2];
            red[a2 + 40] = c0[3];
            int a4 = ((16 + gid) * 8 + 2 * tig) * 40 + rot + w;
            red[a4]      = c1[0];
            red[a4 + 40] = c1[1];
            int a6 = ((24 + gid) * 8 + 2 * tig) * 40 + rot + w;
            red[a6]      = c1[2];
            red[a6 + 40] = c1[3];
        }
        __syncthreads();   // joins all warps => all 32 producer flags >= t observed block-wide

        // ---- reduce 8 partials (2x LDS.128) + epilogue ----
        {
            float4 v0 = *(const float4*)&red[oaddr];
            float4 v1 = *(const float4*)&red[oaddr + 4];
            const float dot = ((v0.x + v0.y) + (v0.z + v0.w))
                            + ((v1.x + v1.y) + (v1.z + v1.w));
            const float raw = wxv + dot + bb;
            const float ex  = __expf(2.f * raw);
            const float hn  = 1.f - 2.f / (ex + 1.f);           // tanh(raw)
            const float gg  = wxv + hn + bgg;
            const float ov  = hn * gg / (1.f + __expf(-gg));    // hn * silu(gg)

            // 1) publish next state FIRST (small L2-resident stores)
            __nv_bfloat16 hi, lo;
            bf16_split(hn, hi, lo);
            __nv_bfloat16* sp = (__nv_bfloat16*)g_spack[g][par ^ 1];
            sp[pub_hi] = hi;
            sp[pub_lo] = lo;

            // 2) release fence: drains ONLY the spack stores (cheap)
            __threadfence();

            // 3) heavy DRAM stores after the fence (fire-and-forget)
            wx_out[gidx] = ov;
            hout[((size_t)(t + 1) * B_DIM + (b0 + bO)) * D_DIM + (e0 + eL)] = hn;
        }
        __syncthreads();   // all threads' spack stores fenced before flag publish
        if (tid == 0) {
            asm volatile("st.global.release.gpu.u32 [%0], %1;"
                         :: "l"(pubflag), "r"((unsigned)(t + 1)) : "memory");
        }

        par ^= 1;
    }
}

// -------------------- launcher --------------------
extern "C" void kernel_launch(void* const* d_in, const int* in_sizes, int n_in,
                              void* d_out, int out_size) {
    const float* x      = (const float*)d_in[0];
    // d_in[1] = z (unused, gate_mode 0)
    const float* h0     = (const float*)d_in[2];
    const float* W_x    = (const float*)d_in[3];
    const float* W_h    = (const float*)d_in[4];
    const float* bvec   = (const float*)d_in[5];
    const float* bgvec  = (const float*)d_in[6];
    const float* u0     = (const float*)d_in[7];

    const int T = in_sizes[0] / (B_DIM * D_DIM);   // 2048
    const int M = T * B_DIM;                       // 65536

    float* out_region = (float*)d_out;                               // [T][B][D]
    float* h_region   = (float*)d_out + (size_t)T * B_DIM * D_DIM;   // [T+1][B][D]

    const size_t gemm_smem = 4 * 128 * GS * sizeof(float);           // 73728 B

    static bool attrs_set = false;
    if (!attrs_set) {
        cudaFuncSetAttribute(gemm_tf32_kernel,
                             cudaFuncAttributeMaxDynamicSharedMemorySize, (int)gemm_smem);
        attrs_set = true;
    }

    wsplit_kernel<<<(D_DIM * D_DIM + 255) / 256, 256>>>(W_x);
    spectral_kernel<<<1, 1024>>>(W_h, u0);
    prep_kernel<<<(B_DIM * D_DIM + 255) / 256, 256>>>(h0, h_region);

    {
        dim3 grid(D_DIM / 128, M / 128);
        gemm_tf32_kernel<<<grid, 256, gemm_smem>>>(x, out_region);
    }

    scan_kernel<<<NBLK, 256>>>(W_h, out_region, h_region, bvec, bgvec, T);
}

// round 17
// speedup vs baseline: 3.8381x; 3.8381x over previous
#include <cuda_runtime.h>
#include <cuda_bf16.h>
#include <math.h>
#include <stdint.h>

// Problem constants
#define D_DIM 1024
#define B_DIM 32
#define NBLK  128      // 4 groups x 32 blocks, 1 CTA/SM, all co-resident
#define NGROUP 4
#define GSZ    32      // blocks per group
#define BSUB   8       // batches per group

// -------------------- device scratch (no cudaMalloc allowed) --------------------
__device__ float g_scale;
// W_x packed bf16 hi/lo in mma-B-fragment layout:
// [nb(128)][k16(64)][lane(32)] -> uint4 (hi_b0, hi_b1, lo_b0, lo_b1)
__device__ uint4 g_WxPack[128 * 64 * 32];
// packed bf16 recurrent state, mma-B-fragment layout:
// [group][parity][sblk(64)][tig(4)][gid(8)] -> uint4 (bhi0,bhi1,blo0,blo1)
__device__ uint32_t g_spack[NGROUP][2][64 * 4 * 8 * 4];
__device__ unsigned g_cnt[NGROUP * 32];            // per-group barrier counters
__device__ volatile unsigned g_genv[NGROUP * 32];  // per-group barrier generations

// -------------------- block-wide sum over 1024 threads --------------------
__device__ __forceinline__ float block_sum1024(float v) {
    __shared__ float sr[32];
    __shared__ float res;
    #pragma unroll
    for (int o = 16; o; o >>= 1) v += __shfl_xor_sync(0xffffffffu, v, o);
    if ((threadIdx.x & 31) == 0) sr[threadIdx.x >> 5] = v;
    __syncthreads();
    if (threadIdx.x < 32) {
        float t = sr[threadIdx.x];
        #pragma unroll
        for (int o = 16; o; o >>= 1) t += __shfl_xor_sync(0xffffffffu, t, o);
        if (threadIdx.x == 0) res = t;
    }
    __syncthreads();
    float out = res;
    __syncthreads();
    return out;
}

// -------------------- 1) spectral norm power iteration --------------------
__global__ void spectral_kernel(const float* __restrict__ Wh,
                                const float* __restrict__ u0) {
    __shared__ float su[D_DIM];
    __shared__ float sv[D_DIM];
    __shared__ float sraw[D_DIM];
    const int tid  = threadIdx.x;
    const int w    = tid >> 5;
    const int lane = tid & 31;

    float x0 = u0[tid];
    float n0 = sqrtf(block_sum1024(x0 * x0));
    su[tid] = x0 / n0;
    __syncthreads();

    for (int it = 0; it < 3; it++) {
        {   // v = W^T u
            float a = 0.f;
            const float* col = Wh + tid;
            #pragma unroll 4
            for (int i = 0; i < D_DIM; i++)
                a = fmaf(col[(size_t)i * D_DIM], su[i], a);
            float nrm = sqrtf(block_sum1024(a * a));
            sv[tid] = a / (nrm + 1e-8f);
            __syncthreads();
        }
        {   // u_raw = W v
            for (int s = 0; s < 32; s++) {
                int r = w * 32 + s;
                const float* row = Wh + (size_t)r * D_DIM;
                float a = 0.f;
                #pragma unroll 4
                for (int k = lane; k < D_DIM; k += 32)
                    a = fmaf(row[k], sv[k], a);
                #pragma unroll
                for (int o = 16; o; o >>= 1) a += __shfl_xor_sync(0xffffffffu, a, o);
                if (lane == 0) sraw[r] = a;
            }
            __syncthreads();
            float rv  = sraw[tid];
            float nrm = sqrtf(block_sum1024(rv * rv));
            su[tid] = rv / (nrm + 1e-8f);
            __syncthreads();
        }
    }
    float sg = block_sum1024(su[tid] * sraw[tid]);
    if (tid == 0) g_scale = 0.99f / (fabsf(sg) + 1e-8f);
}

// -------------------- helpers --------------------
__device__ __forceinline__ void bf16_split(float v, __nv_bfloat16& h, __nv_bfloat16& l) {
    h = __float2bfloat16_rn(v);
    l = __float2bfloat16_rn(v - __bfloat162float(h));
}

// split two floats into packed bf16x2 hi and lo words
__device__ __forceinline__ void bf16_split2(float a, float b, uint32_t& hi, uint32_t& lo) {
    __nv_bfloat16 ah, al_, bh, bl;
    bf16_split(a, ah, al_);
    bf16_split(b, bh, bl);
    __nv_bfloat162 th; th.x = ah; th.y = bh;
    __nv_bfloat162 tl; tl.x = al_; tl.y = bl;
    hi = *(uint32_t*)&th;
    lo = *(uint32_t*)&tl;
}

// bf16-unit index into g_spack for state element (d, n): hi at uoff p>>2, lo at 2+(p>>2)
__device__ __forceinline__ int spack_idx(int d, int n, int is_lo) {
    int sblk = d >> 4;
    int kk   = d & 15;
    int p    = kk >> 1;
    int j    = kk & 1;
    int tigp = p & 3;
    int uoff = (is_lo ? 2 : 0) + (p >> 2);
    return (sblk * 128 + tigp * 32 + n * 4 + uoff) * 2 + j;
}

// -------------------- 2a) pack W_x into bf16 B-fragment layout (once) ------------
__global__ void wpack_kernel(const float* __restrict__ Wx) {
    int i = blockIdx.x * blockDim.x + threadIdx.x;  // uint4 index
    if (i < 128 * 64 * 32) {
        int lane = i & 31;
        int k16  = (i >> 5) & 63;
        int nb   = i >> 11;
        int gid  = lane >> 2, tig = lane & 3;
        int e  = nb * 8 + gid;
        int k0 = k16 * 16 + 2 * tig;
        const float* wr = &Wx[(size_t)e * D_DIM + k0];
        uint32_t x, y, z, ww;
        bf16_split2(wr[0], wr[1], x, z);   // b0: k = 2tig, 2tig+1
        bf16_split2(wr[8], wr[9], y, ww);  // b1: k = 2tig+8, 2tig+9
        g_WxPack[i] = make_uint4(x, y, z, ww);
    }
}

// -------------------- 2b) prep: pack h0 into bf16 state, copy h0 to output ----------
__global__ void prep_kernel(const float* __restrict__ h0,
                            float* __restrict__ hout0) {
    int i = blockIdx.x * blockDim.x + threadIdx.x;
    if (i < B_DIM * D_DIM) {
        int b = i >> 10;
        int d = i & (D_DIM - 1);
        int g = b >> 3;
        int n = b & 7;
        float v = h0[i];
        __nv_bfloat16 hi, lo;
        bf16_split(v, hi, lo);
        __nv_bfloat16* sp = (__nv_bfloat16*)g_spack[g][0];
        sp[spack_idx(d, n, 0)] = hi;
        sp[spack_idx(d, n, 1)] = lo;
        hout0[i] = v;
    }
}

// -------------------- mma helper (shared by GEMM and scan) --------------------
__device__ __forceinline__ void mma_bf16(float* c, const uint32_t* a, uint32_t b0, uint32_t b1) {
    asm volatile(
        "mma.sync.aligned.m16n8k16.row.col.f32.bf16.bf16.f32 "
        "{%0,%1,%2,%3}, {%4,%5,%6,%7}, {%8,%9}, {%0,%1,%2,%3};"
        : "+f"(c[0]), "+f"(c[1]), "+f"(c[2]), "+f"(c[3])
        : "r"(a[0]), "r"(a[1]), "r"(a[2]), "r"(a[3]), "r"(b0), "r"(b1));
}

// -------------------- 3) bf16-split tensor-core GEMM: C[m][e] = sum_d X[m][d] W[e][d] --
// BM=BN=128, BK=64 (4 k16 steps/stage), 256 threads, 8 warps (2m x 4n), warp 64x32.
// B (W_x) pre-packed hi/lo in global B-fragment layout -> LDG.128 straight to mma,
// no smem for B. A (X) staged in smem as packed bf16x2, stride 36 (conflict-free).
// 3 products (hh, hl, lh) recover ~16 mantissa bits; half the mma count of tf32-k8.
#define AST 36   // A smem stride in uint32: bank = 4*gid + tig -> all 32 distinct

__global__ __launch_bounds__(256, 2)
void gemm_bf16_kernel(const float* __restrict__ X,
                      float* __restrict__ C) {
    __shared__ uint32_t Ahs[128 * AST];
    __shared__ uint32_t Als[128 * AST];

    const int tid  = threadIdx.x;
    const int bn   = blockIdx.x * 128;
    const int bm   = blockIdx.y * 128;
    const int wid  = tid >> 5, lane = tid & 31;
    const int wm   = wid >> 2;          // 0..1 : 64-row slab
    const int wn   = wid & 3;           // 0..3 : 32-col slab
    const int gid  = lane >> 2, tig = lane & 3;

    float c[4][4][4];
    #pragma unroll
    for (int mt = 0; mt < 4; mt++)
        #pragma unroll
        for (int nt = 0; nt < 4; nt++)
            #pragma unroll
            for (int r = 0; r < 4; r++) c[mt][nt][r] = 0.f;

    const int sr = tid >> 3;            // staging row base 0..31
    const int sc = (tid & 7) * 4;       // staging float col 0..28
    const int scu = (tid & 7) * 2;      // uint32 col

    for (int k0 = 0; k0 < D_DIM; k0 += 64) {
        __syncthreads();
        // ---- stage X[128][64] -> bf16 hi/lo packed smem ----
        #pragma unroll
        for (int j = 0; j < 4; j++) {
            int row = sr + 32 * j;
            const float* xr = &X[(size_t)(bm + row) * D_DIM + k0];
            #pragma unroll
            for (int h = 0; h < 2; h++) {
                float4 v = *(const float4*)(xr + h * 32 + sc);
                uint32_t h01, l01, h23, l23;
                bf16_split2(v.x, v.y, h01, l01);
                bf16_split2(v.z, v.w, h23, l23);
                int a = row * AST + h * 16 + scu;
                Ahs[a]     = h01;
                Ahs[a + 1] = h23;
                Als[a]     = l01;
                Als[a + 1] = l23;
            }
        }
        __syncthreads();

        #pragma unroll
        for (int ks = 0; ks < 4; ks++) {
            // A fragments for 4 m-tiles (conflict-free LDS)
            uint32_t ah[4][4], al[4][4];
            #pragma unroll
            for (int mt = 0; mt < 4; mt++) {
                int r0 = wm * 64 + mt * 16 + gid;
                int cb = ks * 8 + tig;
                ah[mt][0] = Ahs[r0 * AST + cb];
                ah[mt][1] = Ahs[(r0 + 8) * AST + cb];
                ah[mt][2] = Ahs[r0 * AST + cb + 4];
                ah[mt][3] = Ahs[(r0 + 8) * AST + cb + 4];
                al[mt][0] = Als[r0 * AST + cb];
                al[mt][1] = Als[(r0 + 8) * AST + cb];
                al[mt][2] = Als[r0 * AST + cb + 4];
                al[mt][3] = Als[(r0 + 8) * AST + cb + 4];
            }
            const int k16g = (k0 >> 4) + ks;
            #pragma unroll
            for (int nt = 0; nt < 4; nt++) {
                const uint4 v = __ldg(&g_WxPack[((bn >> 3) + wn * 4 + nt) * 2048 + k16g * 32 + lane]);
                #pragma unroll
                for (int mt = 0; mt < 4; mt++) {
                    mma_bf16(c[mt][nt], ah[mt], v.x, v.y);   // hi * hi
                    mma_bf16(c[mt][nt], ah[mt], v.z, v.w);   // hi * lo
                    mma_bf16(c[mt][nt], al[mt], v.x, v.y);   // lo * hi
                }
            }
        }
    }
    #pragma unroll
    for (int mt = 0; mt < 4; mt++) {
        int row = bm + wm * 64 + mt * 16 + gid;
        #pragma unroll
        for (int nt = 0; nt < 4; nt++) {
            int col = bn + wn * 32 + nt * 8 + 2 * tig;
            *(float2*)&C[(size_t)row * D_DIM + col]       = make_float2(c[mt][nt][0], c[mt][nt][1]);
            *(float2*)&C[(size_t)(row + 8) * D_DIM + col] = make_float2(c[mt][nt][2], c[mt][nt][3]);
        }
    }
}

// -------------------- 4) persistent scan kernel (R10 verbatim: bf16 mma + atomic barrier)
__global__ __launch_bounds__(256, 1)
void scan_kernel(const float* __restrict__ Whmat,
                 float* __restrict__ wx_out,        // [T][B][D]: in = Wx, overwritten with out
                 float* __restrict__ hout,          // [T+1][B][D]
                 const float* __restrict__ bvec,
                 const float* __restrict__ bgvec,
                 int T) {
    __shared__ __align__(16) float red[10240];

    const int tid  = threadIdx.x;
    const int g    = blockIdx.x >> 5;     // group 0..3
    const int r    = blockIdx.x & 31;     // rank in group
    const int e0   = r * 32;
    const int b0   = g * BSUB;
    const int bar  = g * 32;

    const int w    = tid >> 5;            // warp 0..7, covers k in [w*128, w*128+128)
    const int lane = tid & 31;
    const int gid  = lane >> 2;           // 0..7
    const int tig  = lane & 3;            // 0..3

    // ---- preload W A-fragments into registers (hi/lo bf16 split, scaled) ----
    const float s = g_scale;
    uint32_t Ah[2][8][4], Al[2][8][4];
    #pragma unroll
    for (int mt = 0; mt < 2; mt++) {
        #pragma unroll
        for (int ks = 0; ks < 8; ks++) {
            const int k0 = w * 128 + ks * 16 + 2 * tig;
            const int r0 = e0 + mt * 16 + gid;
            #pragma unroll
            for (int i = 0; i < 4; i++) {
                const int rr = r0 + ((i & 1) ? 8 : 0);
                const int kk = k0 + ((i & 2) ? 8 : 0);
                float f0 = Whmat[(size_t)rr * D_DIM + kk]     * s;
                float f1 = Whmat[(size_t)rr * D_DIM + kk + 1] * s;
                __nv_bfloat16 h0b, l0b, h1b, l1b;
                bf16_split(f0, h0b, l0b);
                bf16_split(f1, h1b, l1b);
                __nv_bfloat162 th; th.x = h0b; th.y = h1b;
                __nv_bfloat162 tl; tl.x = l0b; tl.y = l1b;
                Ah[mt][ks][i] = *(uint32_t*)&th;
                Al[mt][ks][i] = *(uint32_t*)&tl;
            }
        }
    }

    // epilogue mapping: thread -> (e = tid&31, b = tid>>5)
    const int eL = tid & 31;
    const int bO = tid >> 5;
    const float bb  = bvec[e0 + eL];
    const float bgg = bgvec[e0 + eL];
    const int oaddr = (eL * 8 + bO) * 40 + (eL & 3) * 8;   // reduce base (slots 0..7)
    const int pub_hi = spack_idx(e0 + eL, bO, 0);
    const int pub_lo = spack_idx(e0 + eL, bO, 1);

    __syncthreads();

    unsigned gen = g_genv[bar];
    int par = 0;

    for (int t = 0; t < T; t++) {
        // prefetch Wx element (DRAM latency overlaps mma loop)
        const size_t gidx = ((size_t)t * B_DIM + (b0 + bO)) * D_DIM + (e0 + eL);
        const float wxv = __ldcg(&wx_out[gidx]);

        float c0[4] = {0.f, 0.f, 0.f, 0.f};
        float c1[4] = {0.f, 0.f, 0.f, 0.f};

        const uint4* bp = (const uint4*)g_spack[g][par];
        #pragma unroll
        for (int ks = 0; ks < 8; ks++) {
            uint4 v = __ldcg(&bp[(w * 8 + ks) * 32 + tig * 8 + gid]);
            // v = (bhi0, bhi1, blo0, blo1)
            mma_bf16(c0, Ah[0][ks], v.x, v.y);
            mma_bf16(c0, Ah[0][ks], v.z, v.w);
            mma_bf16(c0, Al[0][ks], v.x, v.y);
            mma_bf16(c1, Ah[1][ks], v.x, v.y);
            mma_bf16(c1, Ah[1][ks], v.z, v.w);
            mma_bf16(c1, Al[1][ks], v.x, v.y);
        }

        // ---- partials -> smem: value (e_loc, col) at (e_loc*8+col)*40 + (e_loc&3)*8 + w
        {
            const int rot = (gid & 3) * 8;
            int a0 = (gid * 8 + 2 * tig) * 40 + rot + w;
            red[a0]      = c0[0];
            red[a0 + 40] = c0[1];
            int a2 = ((gid + 8) * 8 + 2 * tig) * 40 + rot + w;
            red[a2]      = c0[2];
            red[a2 + 40] = c0[3];
            int a4 = ((16 + gid) * 8 + 2 * tig) * 40 + rot + w;
            red[a4]      = c1[0];
            red[a4 + 40] = c1[1];
            int a6 = ((24 + gid) * 8 + 2 * tig) * 40 + rot + w;
            red[a6]      = c1[2];
            red[a6 + 40] = c1[3];
        }
        __syncthreads();

        // ---- reduce 8 partials (2x LDS.128) + epilogue ----
        {
            float4 v0 = *(const float4*)&red[oaddr];
            float4 v1 = *(const float4*)&red[oaddr + 4];
            const float dot = ((v0.x + v0.y) + (v0.z + v0.w))
                            + ((v1.x + v1.y) + (v1.z + v1.w));
            const float raw = wxv + dot + bb;
            const float ex  = __expf(2.f * raw);
            const float hn  = 1.f - 2.f / (ex + 1.f);           // tanh(raw)
            const float gg  = wxv + hn + bgg;
            const float ov  = hn * gg / (1.f + __expf(-gg));    // hn * silu(gg)
            wx_out[gidx] = ov;
            hout[((size_t)(t + 1) * B_DIM + (b0 + bO)) * D_DIM + (e0 + eL)] = hn;
            // publish next state (bf16 hi/lo, B-fragment layout)
            __nv_bfloat16 hi, lo;
            bf16_split(hn, hi, lo);
            __nv_bfloat16* sp = (__nv_bfloat16*)g_spack[g][par ^ 1];
            sp[pub_hi] = hi;
            sp[pub_lo] = lo;
        }
        __syncthreads();

        // ---- per-group barrier ----
        if (tid == 0) {
            __threadfence();
            if (atomicAdd(&g_cnt[bar], 1u) == GSZ - 1) {
                atomicExch(&g_cnt[bar], 0u);
                __threadfence();
                g_genv[bar] = gen + 1;
            } else {
                while (g_genv[bar] == gen) { }
            }
            gen = gen + 1;
        }
        __syncthreads();
        par ^= 1;
    }
}

// -------------------- launcher --------------------
extern "C" void kernel_launch(void* const* d_in, const int* in_sizes, int n_in,
                              void* d_out, int out_size) {
    const float* x      = (const float*)d_in[0];
    // d_in[1] = z (unused, gate_mode 0)
    const float* h0     = (const float*)d_in[2];
    const float* W_x    = (const float*)d_in[3];
    const float* W_h    = (const float*)d_in[4];
    const float* bvec   = (const float*)d_in[5];
    const float* bgvec  = (const float*)d_in[6];
    const float* u0     = (const float*)d_in[7];

    const int T = in_sizes[0] / (B_DIM * D_DIM);   // 2048
    const int M = T * B_DIM;                       // 65536

    float* out_region = (float*)d_out;                               // [T][B][D]
    float* h_region   = (float*)d_out + (size_t)T * B_DIM * D_DIM;   // [T+1][B][D]

    wpack_kernel<<<(128 * 64 * 32 + 255) / 256, 256>>>(W_x);
    spectral_kernel<<<1, 1024>>>(W_h, u0);
    prep_kernel<<<(B_DIM * D_DIM + 255) / 256, 256>>>(h0, h_region);

    {
        dim3 grid(D_DIM / 128, M / 128);
        gemm_bf16_kernel<<<grid, 256>>>(x, out_region);
    }

    scan_kernel<<<NBLK, 256>>>(W_h, out_region, h_region, bvec, bgvec, T);
}